// round 2
// baseline (speedup 1.0000x reference)
#include <cuda_runtime.h>

// Problem constants (fixed by the reference)
#define G_   131072
#define NPG_ 38
#define NTOT (G_ * NPG_)        // 4,980,736 nodes
#define ETOT (10 * NTOT)        // 49,807,360 edges

// Per-node aggregate scratch (~19.9 MB static device array).
__device__ float g_nodes[NTOT];

// ---------------------------------------------------------------------------
// Kernel 1: g_nodes = x * w_root + b_conv   (float4 vectorized)
// ---------------------------------------------------------------------------
__global__ void init_nodes_kernel(const float* __restrict__ x,
                                  const float* __restrict__ w_root,
                                  const float* __restrict__ b_conv) {
    int i = blockIdx.x * blockDim.x + threadIdx.x;   // over NTOT/4
    const float wr = __ldg(w_root);
    const float bc = __ldg(b_conv);
    float4 v = __ldg(&reinterpret_cast<const float4*>(x)[i]);
    float4 o;
    o.x = fmaf(v.x, wr, bc);
    o.y = fmaf(v.y, wr, bc);
    o.z = fmaf(v.z, wr, bc);
    o.w = fmaf(v.w, wr, bc);
    reinterpret_cast<float4*>(g_nodes)[i] = o;
}

// ---------------------------------------------------------------------------
// Kernel 2: per-edge message + scatter-add.  8 edges/thread.
//   theta = edge_attr * w_edge + b_edge
//   g_nodes[dst] += x[src] * theta        (RED.ADD)
// Edge streams read with __ldcs (evict-first) so they don't thrash the
// L2-resident x / g_nodes working set. Two contiguous vec4 chunks per thread
// keep every streaming load perfectly coalesced while doubling MLP.
// ---------------------------------------------------------------------------
#define EVEC  (ETOT / 4)        // 12,451,840 vec4 edge-groups
#define EHALF (EVEC / 2)        //  6,225,920

__global__ void edge_kernel(const int*   __restrict__ edge_index,
                            const float* __restrict__ edge_attr,
                            const float* __restrict__ x,
                            const float* __restrict__ w_edge,
                            const float* __restrict__ b_edge) {
    int i = blockIdx.x * blockDim.x + threadIdx.x;   // over EHALF
    const int4*   src4 = reinterpret_cast<const int4*>(edge_index);
    const int4*   dst4 = reinterpret_cast<const int4*>(edge_index + ETOT);
    const float4* ea4  = reinterpret_cast<const float4*>(edge_attr);

    // streaming (evict-first) loads of the edge arrays
    int4   s0 = __ldcs(&src4[i]);
    int4   s1 = __ldcs(&src4[i + EHALF]);
    int4   d0 = __ldcs(&dst4[i]);
    int4   d1 = __ldcs(&dst4[i + EHALF]);
    float4 a0 = __ldcs(&ea4[i]);
    float4 a1 = __ldcs(&ea4[i + EHALF]);

    const float we = __ldg(w_edge);
    const float be = __ldg(b_edge);

    // 8 independent gathers first (max MLP), then 8 reductions
    float x0 = __ldg(x + s0.x);
    float x1 = __ldg(x + s0.y);
    float x2 = __ldg(x + s0.z);
    float x3 = __ldg(x + s0.w);
    float x4 = __ldg(x + s1.x);
    float x5 = __ldg(x + s1.y);
    float x6 = __ldg(x + s1.z);
    float x7 = __ldg(x + s1.w);

    atomicAdd(g_nodes + d0.x, x0 * fmaf(a0.x, we, be));
    atomicAdd(g_nodes + d0.y, x1 * fmaf(a0.y, we, be));
    atomicAdd(g_nodes + d0.z, x2 * fmaf(a0.z, we, be));
    atomicAdd(g_nodes + d0.w, x3 * fmaf(a0.w, we, be));
    atomicAdd(g_nodes + d1.x, x4 * fmaf(a1.x, we, be));
    atomicAdd(g_nodes + d1.y, x5 * fmaf(a1.y, we, be));
    atomicAdd(g_nodes + d1.z, x6 * fmaf(a1.z, we, be));
    atomicAdd(g_nodes + d1.w, x7 * fmaf(a1.w, we, be));
}

// ---------------------------------------------------------------------------
// Kernel 3: per-graph head MLP 38 -> 4 -> 4 -> 12 + softmax
// 256 graphs per block, 1 thread per graph; nodes staged via shared
// (padded stride 39 -> conflict-free row reads).
// ---------------------------------------------------------------------------
#define GPB 256
#define ROW 39

__global__ void head_kernel(const float* __restrict__ W1, const float* __restrict__ b1,
                            const float* __restrict__ W2, const float* __restrict__ b2,
                            const float* __restrict__ W3, const float* __restrict__ b3,
                            float* __restrict__ out) {
    __shared__ float sW1[NPG_ * 4];
    __shared__ float sb1[4];
    __shared__ float sW2[16];
    __shared__ float sb2[4];
    __shared__ float sW3[48];
    __shared__ float sb3[12];
    __shared__ float sn[GPB * ROW];

    const int t = threadIdx.x;

    if (t < NPG_ * 4) sW1[t] = W1[t];
    if (t < 4)        sb1[t] = b1[t];
    if (t < 16)       sW2[t] = W2[t];
    if (t >= 32 && t < 36)  sb2[t - 32] = b2[t - 32];
    if (t >= 64 && t < 112) sW3[t - 64] = W3[t - 64];
    if (t >= 128 && t < 140) sb3[t - 128] = b3[t - 128];

    const long long g0 = (long long)blockIdx.x * GPB;
    const float* base = g_nodes + g0 * NPG_;

#pragma unroll 1
    for (int k = t; k < GPB * NPG_; k += blockDim.x) {
        int g = k / NPG_;
        int r = k - g * NPG_;
        sn[g * ROW + r] = __ldcs(base + k);   // dead after this read
    }
    __syncthreads();

    const float* h0 = &sn[t * ROW];

    float h1[4];
#pragma unroll
    for (int j = 0; j < 4; j++) h1[j] = sb1[j];
#pragma unroll
    for (int k = 0; k < NPG_; k++) {
        float v = h0[k];
#pragma unroll
        for (int j = 0; j < 4; j++) h1[j] = fmaf(v, sW1[k * 4 + j], h1[j]);
    }
#pragma unroll
    for (int j = 0; j < 4; j++) h1[j] = (h1[j] >= 0.0f) ? h1[j] : 0.01f * h1[j];

    float h2[4];
#pragma unroll
    for (int j = 0; j < 4; j++) h2[j] = sb2[j];
#pragma unroll
    for (int k = 0; k < 4; k++) {
        float v = h1[k];
#pragma unroll
        for (int j = 0; j < 4; j++) h2[j] = fmaf(v, sW2[k * 4 + j], h2[j]);
    }
#pragma unroll
    for (int j = 0; j < 4; j++) h2[j] = (h2[j] >= 0.0f) ? h2[j] : 0.01f * h2[j];

    float h3[12];
#pragma unroll
    for (int j = 0; j < 12; j++) h3[j] = sb3[j];
#pragma unroll
    for (int k = 0; k < 4; k++) {
        float v = h2[k];
#pragma unroll
        for (int j = 0; j < 12; j++) h3[j] = fmaf(v, sW3[k * 12 + j], h3[j]);
    }
#pragma unroll
    for (int j = 0; j < 12; j++) h3[j] = (h3[j] >= 0.0f) ? h3[j] : 0.01f * h3[j];

    float m = h3[0];
#pragma unroll
    for (int j = 1; j < 12; j++) m = fmaxf(m, h3[j]);
    float ssum = 0.0f;
#pragma unroll
    for (int j = 0; j < 12; j++) {
        h3[j] = __expf(h3[j] - m);
        ssum += h3[j];
    }
    float inv = 1.0f / ssum;

    float* o = out + (g0 + t) * 12;
#pragma unroll
    for (int j = 0; j < 12; j++) o[j] = h3[j] * inv;
}

// ---------------------------------------------------------------------------
// Launch.  Inputs: x, edge_index, edge_attr, w_edge, b_edge, w_root, b_conv,
//                  W1, b1, W2, b2, W3, b3
// ---------------------------------------------------------------------------
extern "C" void kernel_launch(void* const* d_in, const int* in_sizes, int n_in,
                              void* d_out, int out_size) {
    const float* x      = (const float*)d_in[0];
    const int*   ei     = (const int*)  d_in[1];
    const float* ea     = (const float*)d_in[2];
    const float* w_edge = (const float*)d_in[3];
    const float* b_edge = (const float*)d_in[4];
    const float* w_root = (const float*)d_in[5];
    const float* b_conv = (const float*)d_in[6];
    const float* W1     = (const float*)d_in[7];
    const float* b1     = (const float*)d_in[8];
    const float* W2     = (const float*)d_in[9];
    const float* b2     = (const float*)d_in[10];
    const float* W3     = (const float*)d_in[11];
    const float* b3     = (const float*)d_in[12];
    float* out = (float*)d_out;

    init_nodes_kernel<<<(NTOT / 4) / 256, 256>>>(x, w_root, b_conv);
    edge_kernel<<<EHALF / 256, 256>>>(ei, ea, x, w_edge, b_edge);
    head_kernel<<<G_ / GPB, GPB>>>(W1, b1, W2, b2, W3, b3, out);
}

// round 3
// speedup vs baseline: 1.0255x; 1.0255x over previous
#include <cuda_runtime.h>

// Problem constants (fixed by the reference)
#define G_   131072
#define NPG_ 38
#define NTOT (G_ * NPG_)        // 4,980,736 nodes
#define ETOT (10 * NTOT)        // 49,807,360 edges

// Per-node aggregate scratch (~19.9 MB static device array).
// Zeroed by a memset node each replay; edge atomics accumulate into it;
// head kernel adds the root term on read.
__device__ float g_nodes[NTOT];

// ---------------------------------------------------------------------------
// Edge kernel: per-edge message + scatter-add.  4 edges/thread.
//   theta = edge_attr * w_edge + b_edge
//   g_nodes[dst] += x[src] * theta        (RED.ADD, spread addresses)
// Edge streams read with __ldcs (evict-first) so the 600 MB stream does not
// evict the L2-resident x (20 MB) / g_nodes (20 MB) working set.
// Floor: ~1 L1tex wavefront/edge for the gather + ~1.29 cyc/lane REDG.
// ---------------------------------------------------------------------------
#define EVEC (ETOT / 4)         // 12,451,840 vec4 edge-groups

__global__ void __launch_bounds__(256)
edge_kernel(const int*   __restrict__ edge_index,
            const float* __restrict__ edge_attr,
            const float* __restrict__ x,
            const float* __restrict__ w_edge,
            const float* __restrict__ b_edge) {
    int i = blockIdx.x * blockDim.x + threadIdx.x;   // over EVEC
    const int4*   src4 = reinterpret_cast<const int4*>(edge_index);
    const int4*   dst4 = reinterpret_cast<const int4*>(edge_index + ETOT);
    const float4* ea4  = reinterpret_cast<const float4*>(edge_attr);

    int4   s = __ldcs(&src4[i]);
    int4   d = __ldcs(&dst4[i]);
    float4 a = __ldcs(&ea4[i]);

    const float we = __ldg(w_edge);
    const float be = __ldg(b_edge);

    // independent gathers first (MLP), then the reductions
    float x0 = __ldg(x + s.x);
    float x1 = __ldg(x + s.y);
    float x2 = __ldg(x + s.z);
    float x3 = __ldg(x + s.w);

    atomicAdd(g_nodes + d.x, x0 * fmaf(a.x, we, be));
    atomicAdd(g_nodes + d.y, x1 * fmaf(a.y, we, be));
    atomicAdd(g_nodes + d.z, x2 * fmaf(a.z, we, be));
    atomicAdd(g_nodes + d.w, x3 * fmaf(a.w, we, be));
}

// ---------------------------------------------------------------------------
// Head kernel: nodes = g_nodes + x*w_root + b_conv (root term folded in),
// then per-graph MLP 38 -> 4 -> 4 -> 12 + softmax.
// 256 graphs/block, 1 thread per graph. Node block staged through shared via
// float4 loads (GPB*38 floats contiguous, GPB multiple of 4 keeps alignment),
// padded row stride 39 -> conflict-free per-thread row reads.
// ---------------------------------------------------------------------------
#define GPB 256
#define ROW 39

__global__ void __launch_bounds__(GPB)
head_kernel(const float* __restrict__ x,
            const float* __restrict__ w_root, const float* __restrict__ b_conv,
            const float* __restrict__ W1, const float* __restrict__ b1,
            const float* __restrict__ W2, const float* __restrict__ b2,
            const float* __restrict__ W3, const float* __restrict__ b3,
            float* __restrict__ out) {
    __shared__ float sW1[NPG_ * 4];
    __shared__ float sb1[4];
    __shared__ float sW2[16];
    __shared__ float sb2[4];
    __shared__ float sW3[48];
    __shared__ float sb3[12];
    __shared__ float sn[GPB * ROW];

    const int t = threadIdx.x;

    if (t < NPG_ * 4) sW1[t] = W1[t];
    if (t < 4)        sb1[t] = b1[t];
    if (t < 16)       sW2[t] = W2[t];
    if (t >= 32 && t < 36)   sb2[t - 32]  = b2[t - 32];
    if (t >= 64 && t < 112)  sW3[t - 64]  = W3[t - 64];
    if (t >= 128 && t < 140) sb3[t - 128] = b3[t - 128];

    const float wr = __ldg(w_root);
    const float bc = __ldg(b_conv);

    const long long base = (long long)blockIdx.x * (GPB * NPG_);
    const float4* agg4 = reinterpret_cast<const float4*>(g_nodes + base);
    const float4* x4   = reinterpret_cast<const float4*>(x + base);

    // vectorized stage: GPB*38/4 = 2432 float4 per block, fold root term
#pragma unroll 1
    for (int k = t; k < (GPB * NPG_) / 4; k += GPB) {
        float4 av = __ldcs(&agg4[k]);       // dead after this read
        float4 xv = __ldg(&x4[k]);
        int e0 = 4 * k;
        // element e -> shared row e/38, col e%38, stride 39
        int g = e0 / NPG_;
        int r = e0 - g * NPG_;
        float v0 = fmaf(xv.x, wr, bc) + av.x;
        float v1 = fmaf(xv.y, wr, bc) + av.y;
        float v2 = fmaf(xv.z, wr, bc) + av.z;
        float v3 = fmaf(xv.w, wr, bc) + av.w;
        // rows can wrap within a float4; handle per element
        int idx0 = g * ROW + r;
        sn[idx0] = v0;
        int r1 = r + 1, g1 = g;   if (r1 == NPG_) { r1 = 0; g1++; }
        sn[g1 * ROW + r1] = v1;
        int r2 = r1 + 1, g2 = g1; if (r2 == NPG_) { r2 = 0; g2++; }
        sn[g2 * ROW + r2] = v2;
        int r3 = r2 + 1, g3 = g2; if (r3 == NPG_) { r3 = 0; g3++; }
        sn[g3 * ROW + r3] = v3;
    }
    __syncthreads();

    const float* h0 = &sn[t * ROW];

    float h1[4];
#pragma unroll
    for (int j = 0; j < 4; j++) h1[j] = sb1[j];
#pragma unroll
    for (int k = 0; k < NPG_; k++) {
        float v = h0[k];
#pragma unroll
        for (int j = 0; j < 4; j++) h1[j] = fmaf(v, sW1[k * 4 + j], h1[j]);
    }
#pragma unroll
    for (int j = 0; j < 4; j++) h1[j] = (h1[j] >= 0.0f) ? h1[j] : 0.01f * h1[j];

    float h2[4];
#pragma unroll
    for (int j = 0; j < 4; j++) h2[j] = sb2[j];
#pragma unroll
    for (int k = 0; k < 4; k++) {
        float v = h1[k];
#pragma unroll
        for (int j = 0; j < 4; j++) h2[j] = fmaf(v, sW2[k * 4 + j], h2[j]);
    }
#pragma unroll
    for (int j = 0; j < 4; j++) h2[j] = (h2[j] >= 0.0f) ? h2[j] : 0.01f * h2[j];

    float h3[12];
#pragma unroll
    for (int j = 0; j < 12; j++) h3[j] = sb3[j];
#pragma unroll
    for (int k = 0; k < 4; k++) {
        float v = h2[k];
#pragma unroll
        for (int j = 0; j < 12; j++) h3[j] = fmaf(v, sW3[k * 12 + j], h3[j]);
    }
#pragma unroll
    for (int j = 0; j < 12; j++) h3[j] = (h3[j] >= 0.0f) ? h3[j] : 0.01f * h3[j];

    float m = h3[0];
#pragma unroll
    for (int j = 1; j < 12; j++) m = fmaxf(m, h3[j]);
    float ssum = 0.0f;
#pragma unroll
    for (int j = 0; j < 12; j++) {
        h3[j] = __expf(h3[j] - m);
        ssum += h3[j];
    }
    float inv = 1.0f / ssum;

    float* o = out + ((long long)blockIdx.x * GPB + t) * 12;
#pragma unroll
    for (int j = 0; j < 12; j++) o[j] = h3[j] * inv;
}

// ---------------------------------------------------------------------------
// Launch.  Inputs: x, edge_index, edge_attr, w_edge, b_edge, w_root, b_conv,
//                  W1, b1, W2, b2, W3, b3
// ---------------------------------------------------------------------------
extern "C" void kernel_launch(void* const* d_in, const int* in_sizes, int n_in,
                              void* d_out, int out_size) {
    const float* x      = (const float*)d_in[0];
    const int*   ei     = (const int*)  d_in[1];
    const float* ea     = (const float*)d_in[2];
    const float* w_edge = (const float*)d_in[3];
    const float* b_edge = (const float*)d_in[4];
    const float* w_root = (const float*)d_in[5];
    const float* b_conv = (const float*)d_in[6];
    const float* W1     = (const float*)d_in[7];
    const float* b1     = (const float*)d_in[8];
    const float* W2     = (const float*)d_in[9];
    const float* b2     = (const float*)d_in[10];
    const float* W3     = (const float*)d_in[11];
    const float* b3     = (const float*)d_in[12];
    float* out = (float*)d_out;

    // zero the accumulator (memset node, graph-capturable, no allocation)
    void* gnodes_ptr = nullptr;
    cudaGetSymbolAddress(&gnodes_ptr, g_nodes);
    cudaMemsetAsync(gnodes_ptr, 0, NTOT * sizeof(float));

    edge_kernel<<<EVEC / 256, 256>>>(ei, ea, x, w_edge, b_edge);
    head_kernel<<<G_ / GPB, GPB>>>(x, w_root, b_conv,
                                   W1, b1, W2, b2, W3, b3, out);
}

// round 4
// speedup vs baseline: 1.0363x; 1.0106x over previous
#include <cuda_runtime.h>

// Problem constants (fixed by the reference)
#define G_   131072
#define NPG_ 38
#define NTOT (G_ * NPG_)        // 4,980,736 nodes
#define ETOT (10 * NTOT)        // 49,807,360 edges

// Per-node aggregate scratch (~19.9 MB static device array).
// Zeroed by a memset node each replay; edge atomics accumulate into it;
// head kernel adds the root term on read.
__device__ float g_nodes[NTOT];

// ---------------------------------------------------------------------------
// Edge kernel: per-edge message + scatter-add.  4 edges/thread.
//   theta = edge_attr * w_edge + b_edge
//   g_nodes[dst] += x[src] * theta        (RED.ADD, spread addresses)
// At the HW floor: ~2.07 cyc/wavefront L1tex replay for the random gather +
// spread REDG; LTS sector traffic ~3.8 GB also near the 6300 B/cyc cap.
// ---------------------------------------------------------------------------
#define EVEC (ETOT / 4)         // 12,451,840 vec4 edge-groups

__global__ void __launch_bounds__(256)
edge_kernel(const int*   __restrict__ edge_index,
            const float* __restrict__ edge_attr,
            const float* __restrict__ x,
            const float* __restrict__ w_edge,
            const float* __restrict__ b_edge) {
    int i = blockIdx.x * blockDim.x + threadIdx.x;   // over EVEC
    const int4*   src4 = reinterpret_cast<const int4*>(edge_index);
    const int4*   dst4 = reinterpret_cast<const int4*>(edge_index + ETOT);
    const float4* ea4  = reinterpret_cast<const float4*>(edge_attr);

    int4   s = __ldcs(&src4[i]);
    int4   d = __ldcs(&dst4[i]);
    float4 a = __ldcs(&ea4[i]);

    const float we = __ldg(w_edge);
    const float be = __ldg(b_edge);

    // independent gathers first (MLP), then the reductions
    float x0 = __ldg(x + s.x);
    float x1 = __ldg(x + s.y);
    float x2 = __ldg(x + s.z);
    float x3 = __ldg(x + s.w);

    atomicAdd(g_nodes + d.x, x0 * fmaf(a.x, we, be));
    atomicAdd(g_nodes + d.y, x1 * fmaf(a.y, we, be));
    atomicAdd(g_nodes + d.z, x2 * fmaf(a.z, we, be));
    atomicAdd(g_nodes + d.w, x3 * fmaf(a.w, we, be));
}

// ---------------------------------------------------------------------------
// Head kernel: nodes = g_nodes + x*w_root + b_conv (root term folded in),
// then per-graph MLP 38 -> 4 -> 4 -> 12 + softmax.
// 128 graphs/block (grid=1024), 1 thread per graph.
// Node block staged into LINEAR shared via float4 (no padding, no div/mod);
// row reads at stride 38 are only 2-way bank-conflicted. Output packed into
// 3x STG.128 per graph.
// ---------------------------------------------------------------------------
#define GPB   128
#define NVEC  ((GPB * NPG_) / 4)   // 1216 float4 per block

__global__ void __launch_bounds__(GPB)
head_kernel(const float* __restrict__ x,
            const float* __restrict__ w_root, const float* __restrict__ b_conv,
            const float* __restrict__ W1, const float* __restrict__ b1,
            const float* __restrict__ W2, const float* __restrict__ b2,
            const float* __restrict__ W3, const float* __restrict__ b3,
            float* __restrict__ out) {
    __shared__ float sW1[NPG_ * 4];
    __shared__ float sb1[4];
    __shared__ float sW2[16];
    __shared__ float sb2[4];
    __shared__ float sW3[48];
    __shared__ float sb3[12];
    __shared__ float4 sn4[NVEC];               // linear GPB*38 floats

    const int t = threadIdx.x;

    // weight staging (block has 128 threads)
    if (t < 4)   sb1[t] = b1[t];
    if (t < 16)  sW2[t] = W2[t];
    if (t >= 16 && t < 20)  sb2[t - 16] = b2[t - 16];
    if (t >= 32 && t < 44)  sb3[t - 32] = b3[t - 32];
    if (t >= 48 && t < 96)  sW3[t - 48] = W3[t - 48];
    if (t < NPG_ * 4 - 128) sW1[128 + t] = W1[128 + t];  // elems 128..151
    sW1[t] = W1[t];                                      // elems 0..127

    const float wr = __ldg(w_root);
    const float bc = __ldg(b_conv);

    const long long base = (long long)blockIdx.x * (GPB * NPG_);
    const float4* agg4 = reinterpret_cast<const float4*>(g_nodes + base);
    const float4* x4   = reinterpret_cast<const float4*>(x + base);

    // linear staging: fold root term, no index math beyond k
#pragma unroll 1
    for (int k = t; k < NVEC; k += GPB) {
        float4 av = __ldcs(&agg4[k]);     // dead after this read
        float4 xv = __ldg(&x4[k]);
        float4 v;
        v.x = fmaf(xv.x, wr, bc) + av.x;
        v.y = fmaf(xv.y, wr, bc) + av.y;
        v.z = fmaf(xv.z, wr, bc) + av.z;
        v.w = fmaf(xv.w, wr, bc) + av.w;
        sn4[k] = v;
    }
    __syncthreads();

    const float* h0 = reinterpret_cast<const float*>(sn4) + t * NPG_;

    // layer 1: 38 -> 4
    float h1[4];
#pragma unroll
    for (int j = 0; j < 4; j++) h1[j] = sb1[j];
#pragma unroll
    for (int k = 0; k < NPG_; k++) {
        float v = h0[k];
#pragma unroll
        for (int j = 0; j < 4; j++) h1[j] = fmaf(v, sW1[k * 4 + j], h1[j]);
    }
#pragma unroll
    for (int j = 0; j < 4; j++) h1[j] = (h1[j] >= 0.0f) ? h1[j] : 0.01f * h1[j];

    // layer 2: 4 -> 4
    float h2[4];
#pragma unroll
    for (int j = 0; j < 4; j++) h2[j] = sb2[j];
#pragma unroll
    for (int k = 0; k < 4; k++) {
        float v = h1[k];
#pragma unroll
        for (int j = 0; j < 4; j++) h2[j] = fmaf(v, sW2[k * 4 + j], h2[j]);
    }
#pragma unroll
    for (int j = 0; j < 4; j++) h2[j] = (h2[j] >= 0.0f) ? h2[j] : 0.01f * h2[j];

    // layer 3: 4 -> 12
    float h3[12];
#pragma unroll
    for (int j = 0; j < 12; j++) h3[j] = sb3[j];
#pragma unroll
    for (int k = 0; k < 4; k++) {
        float v = h2[k];
#pragma unroll
        for (int j = 0; j < 12; j++) h3[j] = fmaf(v, sW3[k * 12 + j], h3[j]);
    }
#pragma unroll
    for (int j = 0; j < 12; j++) h3[j] = (h3[j] >= 0.0f) ? h3[j] : 0.01f * h3[j];

    // stable softmax over 12
    float m = h3[0];
#pragma unroll
    for (int j = 1; j < 12; j++) m = fmaxf(m, h3[j]);
    float ssum = 0.0f;
#pragma unroll
    for (int j = 0; j < 12; j++) {
        h3[j] = __expf(h3[j] - m);
        ssum += h3[j];
    }
    float inv = 1.0f / ssum;

    // 12 floats = 3x float4 stores (48B-aligned per graph)
    float4* o4 = reinterpret_cast<float4*>(out + ((long long)blockIdx.x * GPB + t) * 12);
    float4 o;
    o.x = h3[0] * inv;  o.y = h3[1] * inv;  o.z = h3[2] * inv;  o.w = h3[3] * inv;
    o4[0] = o;
    o.x = h3[4] * inv;  o.y = h3[5] * inv;  o.z = h3[6] * inv;  o.w = h3[7] * inv;
    o4[1] = o;
    o.x = h3[8] * inv;  o.y = h3[9] * inv;  o.z = h3[10] * inv; o.w = h3[11] * inv;
    o4[2] = o;
}

// ---------------------------------------------------------------------------
// Launch.  Inputs: x, edge_index, edge_attr, w_edge, b_edge, w_root, b_conv,
//                  W1, b1, W2, b2, W3, b3
// ---------------------------------------------------------------------------
extern "C" void kernel_launch(void* const* d_in, const int* in_sizes, int n_in,
                              void* d_out, int out_size) {
    const float* x      = (const float*)d_in[0];
    const int*   ei     = (const int*)  d_in[1];
    const float* ea     = (const float*)d_in[2];
    const float* w_edge = (const float*)d_in[3];
    const float* b_edge = (const float*)d_in[4];
    const float* w_root = (const float*)d_in[5];
    const float* b_conv = (const float*)d_in[6];
    const float* W1     = (const float*)d_in[7];
    const float* b1     = (const float*)d_in[8];
    const float* W2     = (const float*)d_in[9];
    const float* b2     = (const float*)d_in[10];
    const float* W3     = (const float*)d_in[11];
    const float* b3     = (const float*)d_in[12];
    float* out = (float*)d_out;

    // zero the accumulator (memset node, graph-capturable, no allocation)
    void* gnodes_ptr = nullptr;
    cudaGetSymbolAddress(&gnodes_ptr, g_nodes);
    cudaMemsetAsync(gnodes_ptr, 0, NTOT * sizeof(float));

    edge_kernel<<<EVEC / 256, 256>>>(ei, ea, x, w_edge, b_edge);
    head_kernel<<<G_ / GPB, GPB>>>(x, w_root, b_conv,
                                   W1, b1, W2, b2, W3, b3, out);
}